// round 5
// baseline (speedup 1.0000x reference)
#include <cuda_runtime.h>
#include <math.h>

#define H     1024
#define H4    256            // float4 per H row
#define HH2   512
#define V     32000
#define WIN   129
#define NB    148
#define NT    1024
#define NWARP 32
#define NWRP  (NB * NWARP)   // 4736 warps
#define SMAX  4096
#define NEG   -1e30f

// ---------------- persistent scratch ----------------
__device__ float g_t1[HH2];
__device__ float g_sc[SMAX];
__device__ float g_ctx[H];
__device__ float g_pm[NB];
__device__ float g_ps[NB];
__device__ unsigned g_cnt;
__device__ volatile unsigned g_sense;

// ---------------- helpers ----------------
__device__ __forceinline__ float dot4(float4 a, float4 b) {
    return fmaf(a.x, b.x, fmaf(a.y, b.y, fmaf(a.z, b.z, a.w * b.w)));
}
__device__ __forceinline__ float warpSum(float v) {
    #pragma unroll
    for (int o = 16; o > 0; o >>= 1) v += __shfl_xor_sync(0xffffffffu, v, o);
    return v;
}
__device__ __forceinline__ float warpMax(float v) {
    #pragma unroll
    for (int o = 16; o > 0; o >>= 1) v = fmaxf(v, __shfl_xor_sync(0xffffffffu, v, o));
    return v;
}
__device__ __forceinline__ float sigm(float x) { return 1.f / (1.f + expf(-x)); }

// ---------------- grid barrier ----------------
__device__ __forceinline__ void gbar() {
    __syncthreads();
    if (threadIdx.x == 0) {
        unsigned my = g_sense;
        __threadfence();
        if (atomicAdd(&g_cnt, 1u) == NB - 1u) {
            atomicExch(&g_cnt, 0u);
            __threadfence();
            g_sense = my ^ 1u;
        } else {
            while (g_sense == my) { }
            __threadfence();
        }
    }
    __syncthreads();
}

struct Shm {
    float4 xv[H4];       // staged x / h_t / fco
    float4 hv[H4];       // staged h_prev
    float  gate[NWARP];
    float  red[NWARP];
    float  sarr[WIN];
    float  aarr[WIN];
    float  mr[256];
    float  sr[256];
    float  p; int ws, we; float mx, sum;
};

// ---------------- LSTM: 28 warps, 4 gate-warps per unit, 7 units/block ----------------
__device__ __forceinline__ void lstm_layer(
    const float* __restrict__ cprev,
    const float* __restrict__ wih, const float* __restrict__ whh,
    const float* __restrict__ bih, const float* __restrict__ bhh,
    float* __restrict__ hout, float* __restrict__ cout,
    int bid, int wid, int lane, int tid, Shm& sm)
{
    int q = wid >> 2, g = wid & 3;
    int r = bid * 7 + q;
    if (q < 7 && r < H) {
        int row = g * H + r;
        const float4* wi = (const float4*)wih + (size_t)row * H4;
        const float4* wh = (const float4*)whh + (size_t)row * H4;
        float acc = 0.f;
        #pragma unroll
        for (int k = 0; k < 8; k++) {
            int i = lane + 32 * k;
            acc += dot4(__ldcg(wi + i), sm.xv[i]) + dot4(__ldcg(wh + i), sm.hv[i]);
        }
        acc = warpSum(acc);
        if (lane == 0) sm.gate[q * 4 + g] = acc;
    }
    __syncthreads();
    if (tid < 7) {
        int u = bid * 7 + tid;
        if (u < H) {
            float gi = sm.gate[tid * 4 + 0] + bih[u        ] + bhh[u        ];
            float gf = sm.gate[tid * 4 + 1] + bih[u +     H] + bhh[u +     H];
            float gg = sm.gate[tid * 4 + 2] + bih[u + 2 * H] + bhh[u + 2 * H];
            float go = sm.gate[tid * 4 + 3] + bih[u + 3 * H] + bhh[u + 3 * H];
            float c  = sigm(gf) * cprev[u] + sigm(gi) * tanhf(gg);
            cout[u] = c;
            hout[u] = sigm(go) * tanhf(c);
        }
    }
}

// ---------------- the megakernel ----------------
__global__ void __launch_bounds__(NT, 1) decoder_mega(
    const float* __restrict__ enc, const int* __restrict__ word,
    const float* __restrict__ h0,  const float* __restrict__ c0,
    const float* __restrict__ emb,
    const float* __restrict__ wih, const float* __restrict__ whh,
    const float* __restrict__ bih, const float* __restrict__ bhh,
    const float* __restrict__ a1w, const float* __restrict__ a1b,
    const float* __restrict__ a2w, const float* __restrict__ a2b,
    const float* __restrict__ f1w, const float* __restrict__ f1b,
    const float* __restrict__ f2w, const float* __restrict__ f2b,
    float* __restrict__ dout, int S)
{
    __shared__ Shm sm;
    const int tid = threadIdx.x, lane = tid & 31, wid = tid >> 5;
    const int bid = blockIdx.x;
    const int gw  = bid * NWARP + wid;
    const float Sf = (float)S;

    float* y    = dout;
    float* fco  = y   + V;
    float* hn   = fco + H;
    float* cn   = hn  + 2 * H;
    float* aout = cn  + 2 * H;

    // ---- phase 0: LSTM layer 0 ----
    if (tid < 256)      sm.xv[tid]       = ((const float4*)(emb + (size_t)word[0] * H))[tid];
    else if (tid < 512) sm.hv[tid - 256] = ((const float4*)h0)[tid - 256];
    __syncthreads();
    lstm_layer(c0, wih, whh, bih, bhh, hn, cn, bid, wid, lane, tid, sm);
    gbar();

    // ---- phase 1: LSTM layer 1 ----
    if (tid < 256)      sm.xv[tid]       = ((const float4*)hn)[tid];
    else if (tid < 512) sm.hv[tid - 256] = ((const float4*)(h0 + H))[tid - 256];
    __syncthreads();
    lstm_layer(c0 + H, wih + 4 * H * H, whh + 4 * H * H,
               bih + 4 * H, bhh + 4 * H, hn + H, cn + H, bid, wid, lane, tid, sm);
    gbar();

    // ---- phase 2: att_fc1 + full-sequence scores (ht -> sm.xv) ----
    if (tid < 256) sm.xv[tid] = ((const float4*)(hn + H))[tid];
    __syncthreads();
    if (gw < HH2) {
        const float4* w4 = (const float4*)a1w + (size_t)gw * H4;
        float acc = 0.f;
        #pragma unroll
        for (int k = 0; k < 8; k++) { int i = lane + 32 * k; acc += dot4(__ldcg(w4 + i), sm.xv[i]); }
        acc = warpSum(acc);
        if (lane == 0) g_t1[gw] = tanhf(acc + a1b[gw]);
    } else {
        int s = gw - HH2;
        int slim = (S < SMAX) ? S : SMAX;
        if (s < slim) {
            const float4* e4 = (const float4*)(enc + (size_t)s * H);
            float acc = 0.f;
            #pragma unroll
            for (int k = 0; k < 8; k++) { int i = lane + 32 * k; acc += dot4(__ldcg(e4 + i), sm.xv[i]); }
            acc = warpSum(acc);
            if (lane == 0) g_sc[s] = acc;
        }
    }
    if (bid == NB - 1) g_ctx[tid] = 0.f;
    gbar();

    // ---- phase 3: redundant p + window softmax; distributed ctx ----
    {
        float part = (tid < HH2) ? g_t1[tid] * a2w[tid] : 0.f;
        part = warpSum(part);
        if (lane == 0) sm.red[wid] = part;
        __syncthreads();
        if (tid == 0) {
            float s = a2b[0];
            #pragma unroll
            for (int i = 0; i < NWARP; i++) s += sm.red[i];
            float p = Sf * sigm(s);
            sm.p  = p;
            sm.ws = (int)rintf(fmaxf(p - 64.f, 0.f));
            sm.we = (int)rintf(fminf(p + 64.f, Sf - 1.f));
        }
        __syncthreads();
        int ws = sm.ws, we = sm.we;
        if (tid < WIN) {
            int idx = ws + tid;
            sm.sarr[tid] = (idx <= we) ? g_sc[min(idx, S - 1)] : NEG;
        }
        __syncthreads();
        if (tid < 32) {
            float m = NEG;
            for (int i = lane; i < WIN; i += 32) m = fmaxf(m, sm.sarr[i]);
            m = warpMax(m);
            float e = 0.f;
            for (int i = lane; i < WIN; i += 32) e += expf(sm.sarr[i] - m);
            e = warpSum(e);
            if (lane == 0) { sm.mx = m; sm.sum = e; }
        }
        __syncthreads();
        if (tid < WIN) {
            int idx = ws + tid;
            float a = expf(sm.sarr[tid] - sm.mx) / sm.sum;
            float gs = expf(((float)idx - sm.p) * (1.f / 2048.f));
            a = (idx <= we) ? a * gs : 0.f;
            sm.aarr[tid] = a;
            if (bid == 0) aout[tid] = a;
        }
        __syncthreads();
        if (bid < WIN) {
            float a = sm.aarr[bid];
            int idx = min(sm.ws + bid, S - 1);
            atomicAdd(&g_ctx[tid], a * enc[(size_t)idx * H + tid]);
        }
    }
    gbar();

    // ---- phase 4: fc1 (1024 rows x 2048), 7 warps/block spread over blocks ----
    {
        int r = wid * NB + bid;
        if (wid < 7 && r < H) {
            const float4* w4 = (const float4*)f1w + (size_t)r * (2 * H4);
            const float4* c4 = (const float4*)g_ctx;
            float acc = 0.f;
            #pragma unroll
            for (int k = 0; k < 8; k++) { int i = lane + 32 * k; acc += dot4(__ldcg(w4 + i), c4[i]); }
            #pragma unroll
            for (int k = 0; k < 8; k++) { int i = lane + 32 * k; acc += dot4(__ldcg(w4 + 256 + i), sm.xv[i]); }
            acc = warpSum(acc);
            if (lane == 0) fco[r] = tanhf(acc + f1b[r]);
        }
    }
    gbar();

    // ---- phase 5: fc2 (32000 x 1024), two rows per warp + online (max,expsum) ----
    {
        if (tid < 256) sm.xv[tid] = ((const float4*)fco)[tid];
        __syncthreads();
        const float4* w0 = (const float4*)f2w;
        float mw = NEG, sw = 0.f;
        for (int r = gw; r < V; r += 2 * NWRP) {
            int r2 = r + NWRP;
            bool has2 = (r2 < V);
            const float4* wA = w0 + (size_t)r  * H4;
            const float4* wB = w0 + (size_t)r2 * H4;
            float a0 = 0.f, a1 = 0.f;
            #pragma unroll
            for (int k = 0; k < 8; k++) {
                int i = lane + 32 * k;
                float4 xv = sm.xv[i];
                a0 += dot4(__ldcg(wA + i), xv);
                if (has2) a1 += dot4(__ldcg(wB + i), xv);
            }
            a0 = warpSum(a0);
            a1 = warpSum(a1);
            if (lane == 0) {
                float v0 = a0 + f2b[r];
                y[r] = v0;
                float m2 = fmaxf(mw, v0);
                sw = sw * expf(mw - m2) + expf(v0 - m2);
                mw = m2;
                if (has2) {
                    float v1 = a1 + f2b[r2];
                    y[r2] = v1;
                    m2 = fmaxf(mw, v1);
                    sw = sw * expf(mw - m2) + expf(v1 - m2);
                    mw = m2;
                }
            }
        }
        if (lane == 0) { sm.mr[wid] = mw; sm.sr[wid] = sw; }
        __syncthreads();
        if (tid == 0) {
            float M = NEG, Ss = 0.f;
            #pragma unroll
            for (int i = 0; i < NWARP; i++) {
                float m2 = fmaxf(M, sm.mr[i]);
                Ss = Ss * expf(M - m2) + sm.sr[i] * expf(sm.mr[i] - m2);
                M = m2;
            }
            g_pm[bid] = M; g_ps[bid] = Ss;
        }
    }
    gbar();

    // ---- phase 6: combine 148 block partials (fixed tree), subtract lse ----
    {
        if (tid < 256) {
            if (tid < NB) { sm.mr[tid] = g_pm[tid]; sm.sr[tid] = g_ps[tid]; }
            else          { sm.mr[tid] = NEG;       sm.sr[tid] = 0.f; }
        }
        __syncthreads();
        for (int off = 128; off > 0; off >>= 1) {
            if (tid < off) {
                float m1 = sm.mr[tid], m2 = sm.mr[tid + off];
                float m = fmaxf(m1, m2);
                sm.sr[tid] = sm.sr[tid] * expf(m1 - m) + sm.sr[tid + off] * expf(m2 - m);
                sm.mr[tid] = m;
            }
            __syncthreads();
        }
        float lse = sm.mr[0] + logf(sm.sr[0]);
        const int chunk = (V + NB - 1) / NB;     // 217
        int i = bid * chunk + tid;
        if (tid < chunk && i < V) y[i] -= lse;
    }
}

// ---------------- launch ----------------
extern "C" void kernel_launch(void* const* d_in, const int* in_sizes, int n_in,
                              void* d_out, int out_size)
{
    const float* enc  = (const float*)d_in[1];
    const int*   word = (const int*)  d_in[2];
    const float* h0   = (const float*)d_in[3];
    const float* c0   = (const float*)d_in[4];
    const float* emb  = (const float*)d_in[5];
    const float* wih  = (const float*)d_in[6];
    const float* whh  = (const float*)d_in[7];
    const float* bih  = (const float*)d_in[8];
    const float* bhh  = (const float*)d_in[9];
    const float* a1w  = (const float*)d_in[10];
    const float* a1b  = (const float*)d_in[11];
    const float* a2w  = (const float*)d_in[12];
    const float* a2b  = (const float*)d_in[13];
    const float* f1w  = (const float*)d_in[14];
    const float* f1b  = (const float*)d_in[15];
    const float* f2w  = (const float*)d_in[16];
    const float* f2b  = (const float*)d_in[17];

    int S = in_sizes[1] / H;

    decoder_mega<<<NB, NT>>>(enc, word, h0, c0, emb, wih, whh, bih, bhh,
                             a1w, a1b, a2w, a2b, f1w, f1b, f2w, f2b,
                             (float*)d_out, S);
}

// round 6
// speedup vs baseline: 1.0822x; 1.0822x over previous
#include <cuda_runtime.h>
#include <math.h>

#define H     1024
#define H4    256            // float4 per H row
#define HH2   512
#define V     32000
#define WIN   129
#define NB    148
#define NT    1024
#define NWARP 32
#define NWRP  (NB * NWARP)   // 4736 warps
#define NEG   -1e30f
#define CHUNK 217            // ceil(V/NB)

// ---------------- persistent scratch ----------------
__device__ float g_t1[HH2];          // tanh(att_fc1)
__device__ float g_sc[WIN];          // window scores (NEG where invalid)
__device__ float g_ctx[H];           // attention context
__device__ float g_pm[NB];           // per-block logit max
__device__ float g_ps[NB];           // per-block logit expsum
__device__ unsigned g_cnt;
__device__ volatile unsigned g_sense;

// ---------------- helpers ----------------
__device__ __forceinline__ float dot4(float4 a, float4 b) {
    return fmaf(a.x, b.x, fmaf(a.y, b.y, fmaf(a.z, b.z, a.w * b.w)));
}
__device__ __forceinline__ float warpSum(float v) {
    #pragma unroll
    for (int o = 16; o > 0; o >>= 1) v += __shfl_xor_sync(0xffffffffu, v, o);
    return v;
}
__device__ __forceinline__ float warpMax(float v) {
    #pragma unroll
    for (int o = 16; o > 0; o >>= 1) v = fmaxf(v, __shfl_xor_sync(0xffffffffu, v, o));
    return v;
}
__device__ __forceinline__ float sigm(float x) { return 1.f / (1.f + expf(-x)); }

// ---------------- grid barrier (sense-reversing, NB blocks) ----------------
__device__ __forceinline__ void gbar() {
    __syncthreads();
    if (threadIdx.x == 0) {
        unsigned my = g_sense;
        __threadfence();
        if (atomicAdd(&g_cnt, 1u) == NB - 1u) {
            atomicExch(&g_cnt, 0u);
            __threadfence();
            g_sense = my ^ 1u;
        } else {
            while (g_sense == my) { }
            __threadfence();
        }
    }
    __syncthreads();
}

struct Shm {
    float4 xv[H4];      // staged x / h_t / fco
    float4 hv[H4];      // staged h_prev
    float  gate[28];
    float  red[NWARP];
    float  sarr[WIN];
    float  aarr[WIN];
    float  mr[256];
    float  sr[256];
    float  p; int ws, we; float mx, sum;
};

// ---------------- LSTM: 28 warps, 4 gate-warps per unit, 7 units/block ----------------
__device__ __forceinline__ void lstm_layer(
    const float* __restrict__ cprev,
    const float* __restrict__ wih, const float* __restrict__ whh,
    const float* __restrict__ bih, const float* __restrict__ bhh,
    float* __restrict__ hout, float* __restrict__ cout,
    int bid, int wid, int lane, int tid, Shm& sm)
{
    int q = wid >> 2, g = wid & 3;
    int r = bid * 7 + q;
    if (q < 7 && r < H) {
        int row = g * H + r;
        const float4* wi = (const float4*)wih + (size_t)row * H4;
        const float4* wh = (const float4*)whh + (size_t)row * H4;
        float acc = 0.f;
        #pragma unroll
        for (int k = 0; k < 8; k++) {
            int i = lane + 32 * k;
            acc += dot4(wi[i], sm.xv[i]) + dot4(wh[i], sm.hv[i]);
        }
        acc = warpSum(acc);
        if (lane == 0) sm.gate[q * 4 + g] = acc;
    }
    __syncthreads();
    if (tid < 7) {
        int u = bid * 7 + tid;
        if (u < H) {
            float gi = sm.gate[tid * 4 + 0] + bih[u        ] + bhh[u        ];
            float gf = sm.gate[tid * 4 + 1] + bih[u +     H] + bhh[u +     H];
            float gg = sm.gate[tid * 4 + 2] + bih[u + 2 * H] + bhh[u + 2 * H];
            float go = sm.gate[tid * 4 + 3] + bih[u + 3 * H] + bhh[u + 3 * H];
            float c  = sigm(gf) * cprev[u] + sigm(gi) * tanhf(gg);
            cout[u] = c;
            hout[u] = sigm(go) * tanhf(c);
        }
    }
}

// ---------------- the megakernel ----------------
__global__ void __launch_bounds__(NT, 1) decoder_mega(
    const float* __restrict__ enc, const int* __restrict__ word,
    const float* __restrict__ h0,  const float* __restrict__ c0,
    const float* __restrict__ emb,
    const float* __restrict__ wih, const float* __restrict__ whh,
    const float* __restrict__ bih, const float* __restrict__ bhh,
    const float* __restrict__ a1w, const float* __restrict__ a1b,
    const float* __restrict__ a2w, const float* __restrict__ a2b,
    const float* __restrict__ f1w, const float* __restrict__ f1b,
    const float* __restrict__ f2w, const float* __restrict__ f2b,
    float* __restrict__ dout, int S)
{
    __shared__ Shm sm;
    const int tid = threadIdx.x, lane = tid & 31, wid = tid >> 5;
    const int bid = blockIdx.x;
    const int gw  = bid * NWARP + wid;
    const float Sf = (float)S;

    float* y    = dout;
    float* fco  = y   + V;
    float* hn   = fco + H;
    float* cn   = hn  + 2 * H;
    float* aout = cn  + 2 * H;

    // ---- phase 0: LSTM layer 0 ----
    if (tid < 256)      sm.xv[tid]       = ((const float4*)(emb + (size_t)word[0] * H))[tid];
    else if (tid < 512) sm.hv[tid - 256] = ((const float4*)h0)[tid - 256];
    __syncthreads();
    lstm_layer(c0, wih, whh, bih, bhh, hn, cn, bid, wid, lane, tid, sm);
    gbar();

    // ---- phase 1: LSTM layer 1 ----
    if (tid < 256)      sm.xv[tid]       = ((const float4*)hn)[tid];
    else if (tid < 512) sm.hv[tid - 256] = ((const float4*)(h0 + H))[tid - 256];
    __syncthreads();
    lstm_layer(c0 + H, wih + 4 * H * H, whh + 4 * H * H,
               bih + 4 * H, bhh + 4 * H, hn + H, cn + H, bid, wid, lane, tid, sm);
    gbar();

    // ---- phase 2: att_fc1 (512 rows over first 512 warps); stage ht; reset ctx ----
    if (tid < 256) sm.xv[tid] = ((const float4*)(hn + H))[tid];
    __syncthreads();
    if (gw < HH2) {
        const float4* w4 = (const float4*)a1w + (size_t)gw * H4;
        float acc = 0.f;
        #pragma unroll
        for (int k = 0; k < 8; k++) { int i = lane + 32 * k; acc += dot4(w4[i], sm.xv[i]); }
        acc = warpSum(acc);
        if (lane == 0) g_t1[gw] = tanhf(acc + a1b[gw]);
    }
    if (bid == NB - 1) g_ctx[tid] = 0.f;
    gbar();

    // ---- phase 3: redundant p; block b computes window score row b ----
    {
        float part = (tid < HH2) ? g_t1[tid] * a2w[tid] : 0.f;
        part = warpSum(part);
        if (lane == 0) sm.red[wid] = part;
        __syncthreads();
        if (tid == 0) {
            float s = a2b[0];
            #pragma unroll
            for (int i = 0; i < NWARP; i++) s += sm.red[i];
            float p = Sf * sigm(s);
            sm.p  = p;
            sm.ws = (int)rintf(fmaxf(p - 64.f, 0.f));
            sm.we = (int)rintf(fminf(p + 64.f, Sf - 1.f));
        }
        __syncthreads();
        if (bid < WIN) {
            int idx = sm.ws + bid;
            int ic  = min(idx, S - 1);
            // 1024 threads, one float each, block-reduce
            float acc = enc[(size_t)ic * H + tid] * ((const float*)sm.xv)[tid];
            acc = warpSum(acc);
            if (lane == 0) sm.red[wid] = acc;
            __syncthreads();
            if (tid == 0) {
                float s = 0.f;
                #pragma unroll
                for (int i = 0; i < NWARP; i++) s += sm.red[i];
                g_sc[bid] = (idx <= sm.we) ? s : NEG;
            }
        }
    }
    gbar();

    // ---- phase 4: redundant window softmax; distributed ctx; aout ----
    {
        int ws = sm.ws, we = sm.we;
        if (tid < WIN) sm.sarr[tid] = g_sc[tid];
        __syncthreads();
        if (tid < 32) {
            float m = NEG;
            for (int i = lane; i < WIN; i += 32) m = fmaxf(m, sm.sarr[i]);
            m = warpMax(m);
            float e = 0.f;
            for (int i = lane; i < WIN; i += 32) e += expf(sm.sarr[i] - m);
            e = warpSum(e);
            if (lane == 0) { sm.mx = m; sm.sum = e; }
        }
        __syncthreads();
        if (tid < WIN) {
            int idx = ws + tid;
            float a = expf(sm.sarr[tid] - sm.mx) / sm.sum;
            float gs = expf(((float)idx - sm.p) * (1.f / 2048.f));
            a = (idx <= we) ? a * gs : 0.f;
            sm.aarr[tid] = a;
            if (bid == 0) aout[tid] = a;
        }
        __syncthreads();
        if (bid < WIN) {
            float a = sm.aarr[bid];
            int idx = min(ws + bid, S - 1);
            atomicAdd(&g_ctx[tid], a * enc[(size_t)idx * H + tid]);
        }
    }
    gbar();

    // ---- phase 5: fc1 (1024 rows x 2048), 7 warps/block spread over blocks ----
    {
        int r = wid * NB + bid;
        if (wid < 7 && r < H) {
            const float4* w4 = (const float4*)f1w + (size_t)r * (2 * H4);
            const float4* c4 = (const float4*)g_ctx;
            float acc = 0.f;
            #pragma unroll
            for (int k = 0; k < 8; k++) { int i = lane + 32 * k; acc += dot4(w4[i      ], c4[i]); }
            #pragma unroll
            for (int k = 0; k < 8; k++) { int i = lane + 32 * k; acc += dot4(w4[i + 256], sm.xv[i]); }
            acc = warpSum(acc);
            if (lane == 0) fco[r] = tanhf(acc + f1b[r]);
        }
    }
    gbar();

    // ---- phase 6: fc2 (32000 x 1024) — R2's exact loop shape ----
    {
        if (tid < 256) sm.xv[tid] = ((const float4*)fco)[tid];
        __syncthreads();
        for (int r = gw; r < V; r += NWRP) {
            const float4* w4 = (const float4*)f2w + (size_t)r * H4;
            float acc = 0.f;
            #pragma unroll
            for (int k = 0; k < 8; k++) { int i = lane + 32 * k; acc += dot4(w4[i], sm.xv[i]); }
            acc = warpSum(acc);
            if (lane == 0) y[r] = acc + f2b[r];
        }
    }
    gbar();

    // ---- phase 7: per-block (max, expsum) over own 217-logit chunk ----
    {
        int base = bid * CHUNK;
        int i = base + tid;
        bool ok = (tid < CHUNK) && (i < V);
        float v = ok ? y[i] : NEG;
        float m = warpMax(v);
        if (lane == 0) sm.red[wid] = m;
        __syncthreads();
        if (tid == 0) {
            float mm = sm.red[0];
            #pragma unroll
            for (int k = 1; k < NWARP; k++) mm = fmaxf(mm, sm.red[k]);
            sm.mx = mm;
        }
        __syncthreads();
        float mx = sm.mx;
        float e = ok ? expf(v - mx) : 0.f;
        e = warpSum(e);
        __syncthreads();
        if (lane == 0) sm.red[wid] = e;
        __syncthreads();
        if (tid == 0) {
            float ss = 0.f;
            #pragma unroll
            for (int k = 0; k < NWARP; k++) ss += sm.red[k];
            g_pm[bid] = mx; g_ps[bid] = ss;
        }
    }
    gbar();

    // ---- phase 8: combine 148 partials (fixed tree); subtract lse over chunk ----
    {
        if (tid < 256) {
            if (tid < NB) { sm.mr[tid] = g_pm[tid]; sm.sr[tid] = g_ps[tid]; }
            else          { sm.mr[tid] = NEG;       sm.sr[tid] = 0.f; }
        }
        __syncthreads();
        for (int off = 128; off > 0; off >>= 1) {
            if (tid < off) {
                float m1 = sm.mr[tid], m2 = sm.mr[tid + off];
                float m = fmaxf(m1, m2);
                sm.sr[tid] = sm.sr[tid] * expf(m1 - m) + sm.sr[tid + off] * expf(m2 - m);
                sm.mr[tid] = m;
            }
            __syncthreads();
        }
        float lse = sm.mr[0] + logf(sm.sr[0]);
        int i = bid * CHUNK + tid;
        if (tid < CHUNK && i < V) y[i] -= lse;
    }
}

// ---------------- launch ----------------
extern "C" void kernel_launch(void* const* d_in, const int* in_sizes, int n_in,
                              void* d_out, int out_size)
{
    const float* enc  = (const float*)d_in[1];
    const int*   word = (const int*)  d_in[2];
    const float* h0   = (const float*)d_in[3];
    const float* c0   = (const float*)d_in[4];
    const float* emb  = (const float*)d_in[5];
    const float* wih  = (const float*)d_in[6];
    const float* whh  = (const float*)d_in[7];
    const float* bih  = (const float*)d_in[8];
    const float* bhh  = (const float*)d_in[9];
    const float* a1w  = (const float*)d_in[10];
    const float* a1b  = (const float*)d_in[11];
    const float* a2w  = (const float*)d_in[12];
    const float* a2b  = (const float*)d_in[13];
    const float* f1w  = (const float*)d_in[14];
    const float* f1b  = (const float*)d_in[15];
    const float* f2w  = (const float*)d_in[16];
    const float* f2b  = (const float*)d_in[17];

    int S = in_sizes[1] / H;

    decoder_mega<<<NB, NT>>>(enc, word, h0, c0, emb, wih, whh, bih, bhh,
                             a1w, a1b, a2w, a2b, f1w, f1b, f2w, f2b,
                             (float*)d_out, S);
}

// round 7
// speedup vs baseline: 1.1168x; 1.0319x over previous
#include <cuda_runtime.h>
#include <math.h>

#define H     1024
#define H4    256            // float4 per H row
#define HH2   512
#define V     32000
#define WIN   129
#define NB    148
#define NT    1024
#define NWARP 32
#define NWRP  (NB * NWARP)   // 4736 warps
#define SMAX  4096
#define NEG   -1e30f
#define CHUNK 217            // ceil(V/NB)

// ---------------- persistent scratch ----------------
__device__ float g_t1[HH2];          // tanh(att_fc1)
__device__ float g_sc[SMAX];         // full-sequence raw scores
__device__ float g_ctx[H];           // attention context
__device__ float g_pm[NB];           // per-block logit max
__device__ float g_ps[NB];           // per-block logit expsum
__device__ unsigned g_cnt;
__device__ volatile unsigned g_sense;

// ---------------- helpers ----------------
__device__ __forceinline__ float dot4(float4 a, float4 b) {
    return fmaf(a.x, b.x, fmaf(a.y, b.y, fmaf(a.z, b.z, a.w * b.w)));
}
__device__ __forceinline__ float warpSum(float v) {
    #pragma unroll
    for (int o = 16; o > 0; o >>= 1) v += __shfl_xor_sync(0xffffffffu, v, o);
    return v;
}
__device__ __forceinline__ float warpMax(float v) {
    #pragma unroll
    for (int o = 16; o > 0; o >>= 1) v = fmaxf(v, __shfl_xor_sync(0xffffffffu, v, o));
    return v;
}
__device__ __forceinline__ float sigm(float x) { return 1.f / (1.f + expf(-x)); }

// ---------------- grid barrier (sense-reversing, NB blocks) ----------------
__device__ __forceinline__ void gbar() {
    __syncthreads();
    if (threadIdx.x == 0) {
        unsigned my = g_sense;
        __threadfence();
        if (atomicAdd(&g_cnt, 1u) == NB - 1u) {
            atomicExch(&g_cnt, 0u);
            __threadfence();
            g_sense = my ^ 1u;
        } else {
            while (g_sense == my) { }
            __threadfence();
        }
    }
    __syncthreads();
}

struct Shm {
    float4 xv[H4];      // staged x / h_t / fco
    float4 hv[H4];      // staged h_prev
    float  gate[28];
    float  red[NWARP];
    float  sarr[WIN];
    float  aarr[WIN];
    float  mr[256];
    float  sr[256];
    float  p; int ws, we; float mx, sum;
};

// ---------------- LSTM: 28 warps, 4 gate-warps per unit, 7 units/block ----------------
__device__ __forceinline__ void lstm_layer(
    const float* __restrict__ cprev,
    const float* __restrict__ wih, const float* __restrict__ whh,
    const float* __restrict__ bih, const float* __restrict__ bhh,
    float* __restrict__ hout, float* __restrict__ cout,
    int bid, int wid, int lane, int tid, Shm& sm)
{
    int q = wid >> 2, g = wid & 3;
    int r = bid * 7 + q;
    if (q < 7 && r < H) {
        int row = g * H + r;
        const float4* wi = (const float4*)wih + (size_t)row * H4;
        const float4* wh = (const float4*)whh + (size_t)row * H4;
        float acc = 0.f;
        #pragma unroll
        for (int k = 0; k < 8; k++) {
            int i = lane + 32 * k;
            acc += dot4(wi[i], sm.xv[i]) + dot4(wh[i], sm.hv[i]);
        }
        acc = warpSum(acc);
        if (lane == 0) sm.gate[q * 4 + g] = acc;
    }
    __syncthreads();
    if (tid < 7) {
        int u = bid * 7 + tid;
        if (u < H) {
            float gi = sm.gate[tid * 4 + 0] + bih[u        ] + bhh[u        ];
            float gf = sm.gate[tid * 4 + 1] + bih[u +     H] + bhh[u +     H];
            float gg = sm.gate[tid * 4 + 2] + bih[u + 2 * H] + bhh[u + 2 * H];
            float go = sm.gate[tid * 4 + 3] + bih[u + 3 * H] + bhh[u + 3 * H];
            float c  = sigm(gf) * cprev[u] + sigm(gi) * tanhf(gg);
            cout[u] = c;
            hout[u] = sigm(go) * tanhf(c);
        }
    }
}

// ---------------- the megakernel ----------------
__global__ void __launch_bounds__(NT, 1) decoder_mega(
    const float* __restrict__ enc, const int* __restrict__ word,
    const float* __restrict__ h0,  const float* __restrict__ c0,
    const float* __restrict__ emb,
    const float* __restrict__ wih, const float* __restrict__ whh,
    const float* __restrict__ bih, const float* __restrict__ bhh,
    const float* __restrict__ a1w, const float* __restrict__ a1b,
    const float* __restrict__ a2w, const float* __restrict__ a2b,
    const float* __restrict__ f1w, const float* __restrict__ f1b,
    const float* __restrict__ f2w, const float* __restrict__ f2b,
    float* __restrict__ dout, int S)
{
    __shared__ Shm sm;
    const int tid = threadIdx.x, lane = tid & 31, wid = tid >> 5;
    const int bid = blockIdx.x;
    const int gw  = bid * NWARP + wid;
    const float Sf = (float)S;

    float* y    = dout;
    float* fco  = y   + V;
    float* hn   = fco + H;
    float* cn   = hn  + 2 * H;
    float* aout = cn  + 2 * H;

    // ---- phase 0: LSTM layer 0 ----
    if (tid < 256)      sm.xv[tid]       = ((const float4*)(emb + (size_t)word[0] * H))[tid];
    else if (tid < 512) sm.hv[tid - 256] = ((const float4*)h0)[tid - 256];
    __syncthreads();
    lstm_layer(c0, wih, whh, bih, bhh, hn, cn, bid, wid, lane, tid, sm);
    gbar();

    // ---- phase 1: LSTM layer 1 ----
    if (tid < 256)      sm.xv[tid]       = ((const float4*)hn)[tid];
    else if (tid < 512) sm.hv[tid - 256] = ((const float4*)(h0 + H))[tid - 256];
    __syncthreads();
    lstm_layer(c0 + H, wih + 4 * H * H, whh + 4 * H * H,
               bih + 4 * H, bhh + 4 * H, hn + H, cn + H, bid, wid, lane, tid, sm);
    gbar();

    // ---- phase 2: att_fc1 + full-sequence scores (concurrent); stage ht ----
    if (tid < 256) sm.xv[tid] = ((const float4*)(hn + H))[tid];
    __syncthreads();
    if (gw < HH2) {
        const float4* w4 = (const float4*)a1w + (size_t)gw * H4;
        float acc = 0.f;
        #pragma unroll
        for (int k = 0; k < 8; k++) { int i = lane + 32 * k; acc += dot4(w4[i], sm.xv[i]); }
        acc = warpSum(acc);
        if (lane == 0) g_t1[gw] = tanhf(acc + a1b[gw]);
    } else {
        int s = gw - HH2;
        int slim = (S < SMAX) ? S : SMAX;
        if (s < slim) {
            const float4* e4 = (const float4*)(enc + (size_t)s * H);
            float acc = 0.f;
            #pragma unroll
            for (int k = 0; k < 8; k++) { int i = lane + 32 * k; acc += dot4(e4[i], sm.xv[i]); }
            acc = warpSum(acc);
            if (lane == 0) g_sc[s] = acc;
        }
    }
    if (bid == NB - 1) g_ctx[tid] = 0.f;
    gbar();

    // ---- phase 3: redundant p + window softmax; distributed ctx ----
    {
        float part = (tid < HH2) ? g_t1[tid] * a2w[tid] : 0.f;
        part = warpSum(part);
        if (lane == 0) sm.red[wid] = part;
        __syncthreads();
        if (tid == 0) {
            float s = a2b[0];
            #pragma unroll
            for (int i = 0; i < NWARP; i++) s += sm.red[i];
            float p = Sf * sigm(s);
            sm.p  = p;
            sm.ws = (int)rintf(fmaxf(p - 64.f, 0.f));
            sm.we = (int)rintf(fminf(p + 64.f, Sf - 1.f));
        }
        __syncthreads();
        int ws = sm.ws, we = sm.we;
        if (tid < WIN) {
            int idx = ws + tid;
            sm.sarr[tid] = (idx <= we) ? g_sc[min(idx, S - 1)] : NEG;
        }
        __syncthreads();
        if (tid < 32) {
            float m = NEG;
            for (int i = lane; i < WIN; i += 32) m = fmaxf(m, sm.sarr[i]);
            m = warpMax(m);
            float e = 0.f;
            for (int i = lane; i < WIN; i += 32) e += expf(sm.sarr[i] - m);
            e = warpSum(e);
            if (lane == 0) { sm.mx = m; sm.sum = e; }
        }
        __syncthreads();
        if (tid < WIN) {
            int idx = ws + tid;
            float a = expf(sm.sarr[tid] - sm.mx) / sm.sum;
            float gs = expf(((float)idx - sm.p) * (1.f / 2048.f));
            a = (idx <= we) ? a * gs : 0.f;
            sm.aarr[tid] = a;
            if (bid == 0) aout[tid] = a;
        }
        __syncthreads();
        if (bid < WIN) {
            float a = sm.aarr[bid];
            int idx = min(sm.ws + bid, S - 1);
            atomicAdd(&g_ctx[tid], a * enc[(size_t)idx * H + tid]);
        }
    }
    gbar();

    // ---- phase 4: fc1 (1024 rows x 2048), 7 warps/block spread over blocks ----
    {
        int r = wid * NB + bid;
        if (wid < 7 && r < H) {
            const float4* w4 = (const float4*)f1w + (size_t)r * (2 * H4);
            const float4* c4 = (const float4*)g_ctx;
            float acc = 0.f;
            #pragma unroll
            for (int k = 0; k < 8; k++) { int i = lane + 32 * k; acc += dot4(w4[i      ], c4[i]); }
            #pragma unroll
            for (int k = 0; k < 8; k++) { int i = lane + 32 * k; acc += dot4(w4[i + 256], sm.xv[i]); }
            acc = warpSum(acc);
            if (lane == 0) fco[r] = tanhf(acc + f1b[r]);
        }
    }
    gbar();

    // ---- phase 5: fc2 (32000 x 1024), two ADJACENT rows per warp, no tail ----
    {
        if (tid < 256) sm.xv[tid] = ((const float4*)fco)[tid];
        __syncthreads();
        const float4* w0 = (const float4*)f2w;
        for (int r = 2 * gw; r < V; r += 2 * NWRP) {
            const float4* wA = w0 + (size_t)r * H4;
            const float4* wB = wA + H4;
            float a0 = 0.f, a1 = 0.f;
            #pragma unroll
            for (int k = 0; k < 8; k++) {
                int i = lane + 32 * k;
                float4 xv = sm.xv[i];
                a0 += dot4(wA[i], xv);
                a1 += dot4(wB[i], xv);
            }
            a0 = warpSum(a0);
            a1 = warpSum(a1);
            if (lane == 0) {
                y[r    ] = a0 + f2b[r    ];
                y[r + 1] = a1 + f2b[r + 1];
            }
        }
    }
    gbar();

    // ---- phase 6: per-block (max, expsum) over own 217-logit chunk ----
    {
        int i = bid * CHUNK + tid;
        bool ok = (tid < CHUNK) && (i < V);
        float v = ok ? y[i] : NEG;
        float m = warpMax(v);
        if (lane == 0) sm.red[wid] = m;
        __syncthreads();
        if (tid == 0) {
            float mm = sm.red[0];
            #pragma unroll
            for (int k = 1; k < NWARP; k++) mm = fmaxf(mm, sm.red[k]);
            sm.mx = mm;
        }
        __syncthreads();
        float mx = sm.mx;
        float e = ok ? expf(v - mx) : 0.f;
        e = warpSum(e);
        __syncthreads();
        if (lane == 0) sm.red[wid] = e;
        __syncthreads();
        if (tid == 0) {
            float ss = 0.f;
            #pragma unroll
            for (int k = 0; k < NWARP; k++) ss += sm.red[k];
            g_pm[bid] = mx; g_ps[bid] = ss;
        }
    }
    gbar();

    // ---- phase 7: combine 148 partials (fixed tree); subtract lse over chunk ----
    {
        if (tid < 256) {
            if (tid < NB) { sm.mr[tid] = g_pm[tid]; sm.sr[tid] = g_ps[tid]; }
            else          { sm.mr[tid] = NEG;       sm.sr[tid] = 0.f; }
        }
        __syncthreads();
        for (int off = 128; off > 0; off >>= 1) {
            if (tid < off) {
                float m1 = sm.mr[tid], m2 = sm.mr[tid + off];
                float m = fmaxf(m1, m2);
                sm.sr[tid] = sm.sr[tid] * expf(m1 - m) + sm.sr[tid + off] * expf(m2 - m);
                sm.mr[tid] = m;
            }
            __syncthreads();
        }
        float lse = sm.mr[0] + logf(sm.sr[0]);
        int i = bid * CHUNK + tid;
        if (tid < CHUNK && i < V) y[i] -= lse;
    }
}

// ---------------- launch ----------------
extern "C" void kernel_launch(void* const* d_in, const int* in_sizes, int n_in,
                              void* d_out, int out_size)
{
    const float* enc  = (const float*)d_in[1];
    const int*   word = (const int*)  d_in[2];
    const float* h0   = (const float*)d_in[3];
    const float* c0   = (const float*)d_in[4];
    const float* emb  = (const float*)d_in[5];
    const float* wih  = (const float*)d_in[6];
    const float* whh  = (const float*)d_in[7];
    const float* bih  = (const float*)d_in[8];
    const float* bhh  = (const float*)d_in[9];
    const float* a1w  = (const float*)d_in[10];
    const float* a1b  = (const float*)d_in[11];
    const float* a2w  = (const float*)d_in[12];
    const float* a2b  = (const float*)d_in[13];
    const float* f1w  = (const float*)d_in[14];
    const float* f1b  = (const float*)d_in[15];
    const float* f2w  = (const float*)d_in[16];
    const float* f2b  = (const float*)d_in[17];

    int S = in_sizes[1] / H;

    decoder_mega<<<NB, NT>>>(enc, word, h0, c0, emb, wih, whh, bih, bhh,
                             a1w, a1b, a2w, a2b, f1w, f1b, f2w, f2b,
                             (float*)d_out, S);
}

// round 8
// speedup vs baseline: 1.1402x; 1.0210x over previous
#include <cuda_runtime.h>
#include <math.h>

#define H      1024
#define H4     (H/4)          // 256 float4 per H row
#define HH2    512
#define V      32000
#define WIN    129
#define NB     148
#define NT     1024
#define NWRP   (NB * 32)       // 4736 warps
#define SMAX   4096
#define NEG    -1e30f
#define CHUNK  217             // ceil(V/NB)

// ---------------- persistent scratch (no allocation allowed) ----------------
__device__ float g_t1[HH2];          // tanh(att_fc1)
__device__ float g_sc[SMAX];         // full-sequence raw scores
__device__ float g_ctx[H];           // attention context (atomicAdd target)
__device__ float g_pm[NB];           // per-block logit max
__device__ float g_ps[NB];           // per-block logit expsum
__device__ unsigned g_cnt;           // barrier arrival counter
__device__ volatile unsigned g_sense;// barrier sense flag

// ---------------- helpers ----------------
__device__ __forceinline__ float dot4(float4 a, float4 b) {
    return fmaf(a.x, b.x, fmaf(a.y, b.y, fmaf(a.z, b.z, a.w * b.w)));
}
__device__ __forceinline__ float warpSum(float v) {
    #pragma unroll
    for (int o = 16; o > 0; o >>= 1) v += __shfl_xor_sync(0xffffffffu, v, o);
    return v;
}
__device__ __forceinline__ float warpMax(float v) {
    #pragma unroll
    for (int o = 16; o > 0; o >>= 1) v = fmaxf(v, __shfl_xor_sync(0xffffffffu, v, o));
    return v;
}
__device__ __forceinline__ float sigm(float x) { return 1.f / (1.f + expf(-x)); }
__device__ __forceinline__ void prefetchL2(const void* p) {
    asm volatile("prefetch.global.L2 [%0];" :: "l"(p));
}

// ---------------- grid barrier (sense-reversing, all NB blocks) ----------------
__device__ __forceinline__ void gbar() {
    __syncthreads();
    if (threadIdx.x == 0) {
        unsigned my = g_sense;                 // volatile read
        __threadfence();                       // release prior writes
        if (atomicAdd(&g_cnt, 1u) == NB - 1u) {
            atomicExch(&g_cnt, 0u);            // reset for next barrier
            __threadfence();
            g_sense = my ^ 1u;                 // release
        } else {
            while (g_sense == my) { }          // volatile poll
            __threadfence();                   // acquire
        }
    }
    __syncthreads();
}

struct Shm {
    float gate[28];      // 7 rows x 4 gates
    float red[32];
    float sarr[WIN];
    float aarr[WIN];
    float mr[256];
    float sr[256];
    float p;
    int   ws, we;
    float mx, sum;
};

// ---------------- LSTM layer: 28 warps/block, 4 gate-warps per row (R2 verbatim) ----------------
__device__ __forceinline__ void lstm_layer(
    const float4* __restrict__ x4, const float4* __restrict__ h4,
    const float* __restrict__ cprev,
    const float* __restrict__ wih, const float* __restrict__ whh,
    const float* __restrict__ bih, const float* __restrict__ bhh,
    float* __restrict__ hout, float* __restrict__ cout,
    int bid, int wid, int lane, Shm& sm)
{
    int q = wid >> 2;            // local row 0..7
    int gate = wid & 3;
    int r = bid * 7 + q;
    if (q < 7 && r < H) {
        const float4* wi = (const float4*)wih + ((size_t)gate * H + r) * H4;
        const float4* wh = (const float4*)whh + ((size_t)gate * H + r) * H4;
        float acc = 0.f;
        #pragma unroll
        for (int k = 0; k < 8; k++) {
            int i = lane + 32 * k;
            acc += dot4(wi[i], x4[i]) + dot4(wh[i], h4[i]);
        }
        acc = warpSum(acc);
        if (lane == 0) sm.gate[q * 4 + gate] = acc;
    }
    __syncthreads();
    int t = threadIdx.x;
    if (t < 7) {
        int r2 = bid * 7 + t;
        if (r2 < H) {
            float gi = sm.gate[t * 4 + 0] + bih[r2        ] + bhh[r2        ];
            float gf = sm.gate[t * 4 + 1] + bih[r2 +     H] + bhh[r2 +     H];
            float gg = sm.gate[t * 4 + 2] + bih[r2 + 2 * H] + bhh[r2 + 2 * H];
            float go = sm.gate[t * 4 + 3] + bih[r2 + 3 * H] + bhh[r2 + 3 * H];
            float c  = sigm(gf) * cprev[r2] + sigm(gi) * tanhf(gg);
            cout[r2] = c;
            hout[r2] = sigm(go) * tanhf(c);
        }
    }
}

// ---------------- the megakernel ----------------
__global__ void __launch_bounds__(NT, 1) decoder_mega(
    const float* __restrict__ enc, const int* __restrict__ word,
    const float* __restrict__ h0,  const float* __restrict__ c0,
    const float* __restrict__ emb,
    const float* __restrict__ wih, const float* __restrict__ whh,
    const float* __restrict__ bih, const float* __restrict__ bhh,
    const float* __restrict__ a1w, const float* __restrict__ a1b,
    const float* __restrict__ a2w, const float* __restrict__ a2b,
    const float* __restrict__ f1w, const float* __restrict__ f1b,
    const float* __restrict__ f2w, const float* __restrict__ f2b,
    float* __restrict__ dout, int S)
{
    __shared__ Shm sm;
    const int tid = threadIdx.x, lane = tid & 31, wid = tid >> 5;
    const int bid = blockIdx.x;
    const int gw  = bid * 32 + wid;
    const float Sf = (float)S;

    float* y    = dout;              // [V]
    float* fco  = y   + V;           // [H]
    float* hn   = fco + H;           // [2,H]
    float* cn   = hn  + 2 * H;       // [2,H]
    float* aout = cn  + 2 * H;       // [WIN]

    // ---- phase 0: LSTM layer 0 (x = embedding[word]) ----
    {
        const float4* x4 = (const float4*)(emb + (size_t)word[0] * H);
        const float4* h4 = (const float4*)h0;
        lstm_layer(x4, h4, c0, wih, whh, bih, bhh, hn, cn, bid, wid, lane, sm);
    }
    gbar();

    // ---- phase 1: LSTM layer 1 (x = h of layer 0) ----
    {
        const float4* x4 = (const float4*)hn;
        const float4* h4 = (const float4*)(h0 + H);
        lstm_layer(x4, h4, c0 + H, wih + 4 * H * H, whh + 4 * H * H,
                   bih + 4 * H, bhh + 4 * H, hn + H, cn + H, bid, wid, lane, sm);
    }
    gbar();

    const float* ht = hn + H;
    const float4* ht4 = (const float4*)ht;

    // ---- phase 2: att_fc1 (512 rows) + full-sequence scores + scratch reset ----
    if (gw < HH2) {
        const float4* w4 = (const float4*)a1w + (size_t)gw * H4;
        float acc = 0.f;
        #pragma unroll
        for (int k = 0; k < 8; k++) { int i = lane + 32 * k; acc += dot4(w4[i], ht4[i]); }
        acc = warpSum(acc);
        if (lane == 0) g_t1[gw] = tanhf(acc + a1b[gw]);
    } else {
        int s = gw - HH2;
        int slim = (S < SMAX) ? S : SMAX;
        if (s < slim) {
            const float4* e4 = (const float4*)(enc + (size_t)s * H);
            float acc = 0.f;
            #pragma unroll
            for (int k = 0; k < 8; k++) { int i = lane + 32 * k; acc += dot4(e4[i], ht4[i]); }
            acc = warpSum(acc);
            if (lane == 0) g_sc[s] = acc;
        }
    }
    if (bid == NB - 1) g_ctx[tid] = 0.f;
    gbar();

    // ---- phase 3: redundant p + window softmax; distributed ctx ----
    {
        float part = (tid < HH2) ? g_t1[tid] * a2w[tid] : 0.f;
        part = warpSum(part);
        if (lane == 0) sm.red[wid] = part;
        __syncthreads();
        if (tid == 0) {
            float s = a2b[0];
            #pragma unroll
            for (int i = 0; i < 32; i++) s += sm.red[i];
            float p = Sf * sigm(s);
            sm.p  = p;
            sm.ws = (int)rintf(fmaxf(p - 64.f, 0.f));
            sm.we = (int)rintf(fminf(p + 64.f, Sf - 1.f));
        }
        __syncthreads();
        int ws = sm.ws, we = sm.we;
        if (tid < WIN) {
            int idx = ws + tid;
            int ic  = min(idx, S - 1);
            sm.sarr[tid] = (idx <= we) ? g_sc[ic] : NEG;
        }
        __syncthreads();
        if (tid < 32) {
            float m = NEG;
            for (int i = lane; i < WIN; i += 32) m = fmaxf(m, sm.sarr[i]);
            m = warpMax(m);
            float e = 0.f;
            for (int i = lane; i < WIN; i += 32) e += expf(sm.sarr[i] - m);
            e = warpSum(e);
            if (lane == 0) { sm.mx = m; sm.sum = e; }
        }
        __syncthreads();
        if (tid < WIN) {
            int idx = ws + tid;
            float a = expf(sm.sarr[tid] - sm.mx) / sm.sum;
            float gss = expf(((float)idx - sm.p) * (1.f / 2048.f));
            a = (idx <= we) ? a * gss : 0.f;
            sm.aarr[tid] = a;
            if (bid == 0) aout[tid] = a;
        }
        __syncthreads();
        if (bid < WIN) {                 // block b accumulates window row b
            float a = sm.aarr[bid];
            int idx = min(sm.ws + bid, S - 1);
            atomicAdd(&g_ctx[tid], a * enc[(size_t)idx * H + tid]);
        }
    }
    gbar();

    // ---- phase 4: fc1 (1024 rows x 2048), rows spread over all blocks ----
    {
        int r = wid * NB + bid;
        if (wid < 7 && r < H) {
            const float4* w4 = (const float4*)f1w + (size_t)r * (2 * H4);
            const float4* c4 = (const float4*)g_ctx;
            float acc = 0.f;
            #pragma unroll
            for (int k = 0; k < 8; k++) { int i = lane + 32 * k; acc += dot4(w4[i      ], c4[i]); }
            #pragma unroll
            for (int k = 0; k < 8; k++) { int i = lane + 32 * k; acc += dot4(w4[i + 256], ht4[i]); }
            acc = warpSum(acc);
            if (lane == 0) fco[r] = tanhf(acc + f1b[r]);
        }
    }
    gbar();

    // ---- phase 5: fc2 (32000 x 1024) — R2's loop + next-row L2 prefetch ----
    {
        const float4* x4 = (const float4*)fco;
        const char* wbase = (const char*)f2w;
        // warm the pipe: prefetch this warp's first row
        prefetchL2(wbase + (size_t)gw * 4096 + lane * 128);
        for (int r = gw; r < V; r += NWRP) {
            // prefetch NEXT row (32 lanes x 128B = full 4KB row) while computing this one
            if (r + NWRP < V)
                prefetchL2(wbase + (size_t)(r + NWRP) * 4096 + lane * 128);
            const float4* w4 = (const float4*)f2w + (size_t)r * H4;
            float acc = 0.f;
            #pragma unroll
            for (int k = 0; k < 8; k++) { int i = lane + 32 * k; acc += dot4(w4[i], x4[i]); }
            acc = warpSum(acc);
            if (lane == 0) y[r] = acc + f2b[r];
        }
    }
    gbar();

    // ---- phase 6: per-block (max, expsum) over own 217-logit chunk ----
    {
        int i = bid * CHUNK + tid;
        bool ok = (tid < CHUNK) && (i < V);
        float v = ok ? y[i] : NEG;
        float m = warpMax(v);
        if (lane == 0) sm.red[wid] = m;
        __syncthreads();
        if (tid == 0) {
            float mm = sm.red[0];
            #pragma unroll
            for (int k = 1; k < 32; k++) mm = fmaxf(mm, sm.red[k]);
            sm.mx = mm;
        }
        __syncthreads();
        float mx = sm.mx;
        float e = ok ? expf(v - mx) : 0.f;
        e = warpSum(e);
        __syncthreads();
        if (lane == 0) sm.red[wid] = e;
        __syncthreads();
        if (tid == 0) {
            float ss = 0.f;
            #pragma unroll
            for (int k = 0; k < 32; k++) ss += sm.red[k];
            g_pm[bid] = mx; g_ps[bid] = ss;
        }
    }
    gbar();

    // ---- phase 7: combine 148 partials (fixed tree); subtract lse over chunk ----
    {
        if (tid < 256) {
            if (tid < NB) { sm.mr[tid] = g_pm[tid]; sm.sr[tid] = g_ps[tid]; }
            else          { sm.mr[tid] = NEG;       sm.sr[tid] = 0.f; }
        }
        __syncthreads();
        for (int off = 128; off > 0; off >>= 1) {
            if (tid < off) {
                float m1 = sm.mr[tid], m2 = sm.mr[tid + off];
                float m = fmaxf(m1, m2);
                sm.sr[tid] = sm.sr[tid] * expf(m1 - m) + sm.sr[tid + off] * expf(m2 - m);
                sm.mr[tid] = m;
            }
            __syncthreads();
        }
        float lse = sm.mr[0] + logf(sm.sr[0]);
        int i = bid * CHUNK + tid;
        if (tid < CHUNK && i < V) y[i] -= lse;
    }
}

// ---------------- launch ----------------
extern "C" void kernel_launch(void* const* d_in, const int* in_sizes, int n_in,
                              void* d_out, int out_size)
{
    const float* enc  = (const float*)d_in[1];
    const int*   word = (const int*)  d_in[2];
    const float* h0   = (const float*)d_in[3];
    const float* c0   = (const float*)d_in[4];
    const float* emb  = (const float*)d_in[5];
    const float* wih  = (const float*)d_in[6];
    const float* whh  = (const float*)d_in[7];
    const float* bih  = (const float*)d_in[8];
    const float* bhh  = (const float*)d_in[9];
    const float* a1w  = (const float*)d_in[10];
    const float* a1b  = (const float*)d_in[11];
    const float* a2w  = (const float*)d_in[12];
    const float* a2b  = (const float*)d_in[13];
    const float* f1w  = (const float*)d_in[14];
    const float* f1b  = (const float*)d_in[15];
    const float* f2w  = (const float*)d_in[16];
    const float* f2b  = (const float*)d_in[17];

    int S = in_sizes[1] / H;

    decoder_mega<<<NB, NT>>>(enc, word, h0, c0, emb, wih, whh, bih, bhh,
                             a1w, a1b, a2w, a2b, f1w, f1b, f2w, f2b,
                             (float*)d_out, S);
}